// round 6
// baseline (speedup 1.0000x reference)
#include <cuda_runtime.h>

#define NUM_P 4
#define NUM_B 256
#define NUM_N 65536
#define NUM_D 256
#define KTOP  10
#define SCALE_F 10.0f

#define BM 64
#define BN 128
#define BK 16
#define TILES_PER_CHUNK 4
#define CHUNK_N (BN * TILES_PER_CHUNK)   // 512
#define NCHUNKS (NUM_N / CHUNK_N)        // 128
#define DT_LD 132

#define INF_F __int_as_float(0x7f800000)

struct Partial {
    float v[KTOP];
    int   id[KTOP];
    float m;
    float s;
};

// static scratch (no allocations allowed)
__device__ Partial g_part[NUM_P * NUM_B * NCHUNKS];   // ~11.5 MB
__device__ float   g_cnorm[NUM_P * NUM_N];            // 1 MB
__device__ float   g_rowdiff[NUM_P * NUM_B];          // 4 KB

// ---------------------------------------------------------------------------
// helpers
// ---------------------------------------------------------------------------
__device__ __forceinline__ void topk_insert(float v, int idx, float* tv, int* ti) {
    if (v < tv[KTOP - 1]) {
        tv[KTOP - 1] = v; ti[KTOP - 1] = idx;
        #pragma unroll
        for (int i = KTOP - 1; i > 0; --i) {
            if (tv[i] < tv[i - 1]) {
                float t = tv[i]; tv[i] = tv[i - 1]; tv[i - 1] = t;
                int   u = ti[i]; ti[i] = ti[i - 1]; ti[i - 1] = u;
            }
        }
    }
}

// running logsumexp of exp(-SCALE*d): state (m = min d, s = sum exp(-SCALE*(d-m)))
__device__ __forceinline__ void lse_merge(float& m, float& s, float m2, float s2) {
    if (m2 < m) {
        s = s * expf(SCALE_F * (m2 - m)) + s2;
        m = m2;
    } else {
        s = s + s2 * expf(SCALE_F * (m - m2));
    }
}

// ---------------------------------------------------------------------------
// kernel 1: per-center squared norms
// ---------------------------------------------------------------------------
__global__ void cnorm_kernel(const float* __restrict__ centers) {
    int warp = (blockIdx.x * blockDim.x + threadIdx.x) >> 5;
    int lane = threadIdx.x & 31;
    if (warp >= NUM_P * NUM_N) return;
    const float4* row = (const float4*)(centers + (size_t)warp * NUM_D);
    float s = 0.0f;
    #pragma unroll
    for (int i = 0; i < 2; ++i) {
        float4 v = row[lane + i * 32];
        s += v.x * v.x + v.y * v.y + v.z * v.z + v.w * v.w;
    }
    #pragma unroll
    for (int o = 16; o; o >>= 1) s += __shfl_xor_sync(0xffffffffu, s, o);
    if (lane == 0) g_cnorm[warp] = s;
}

// ---------------------------------------------------------------------------
// kernel 2: fused distance-GEMM + per-row top-K + online LSE -> partials
//   grid: (NCHUNKS, NUM_B/BM, NUM_P), 256 threads
// ---------------------------------------------------------------------------
__global__ __launch_bounds__(256, 2)
void main_kernel(const float* __restrict__ feature,
                 const float* __restrict__ centers,
                 const int*   __restrict__ position)
{
    __shared__ float As[BK][BM];        // 4 KB
    __shared__ float Bs[BK][BN];        // 8 KB
    __shared__ float dt[BM * DT_LD];    // 33 KB (also overlaid by merge arrays)
    __shared__ float s_cn[BN];

    const int p     = blockIdx.z;
    const int rg    = blockIdx.y;
    const int chunk = blockIdx.x;
    const int b0    = rg * BM;
    const int tid   = threadIdx.x;
    const int ty    = tid >> 4;     // 0..15 (4 rows each)
    const int tx    = tid & 15;     // 0..15 (8 cols each)
    const int srow  = tid >> 2;     // 0..63 scan row
    const int sq    = tid & 3;      // quarter of the 128 cols

    const int mypos = position[b0 + srow];

    float tv[KTOP]; int ti[KTOP];
    #pragma unroll
    for (int i = 0; i < KTOP; ++i) { tv[i] = INF_F; ti[i] = -1; }
    float lm = INF_F, ls = 0.0f;

    const float* fbase = feature + ((size_t)p * NUM_B + b0) * NUM_D;

    for (int t = 0; t < TILES_PER_CHUNK; ++t) {
        const int n0 = chunk * CHUNK_N + t * BN;
        const float* cbase = centers + ((size_t)p * NUM_N + n0) * NUM_D;

        float acc[4][8];
        #pragma unroll
        for (int i = 0; i < 4; ++i)
            #pragma unroll
            for (int j = 0; j < 8; ++j) acc[i][j] = 0.0f;

        for (int kt = 0; kt < NUM_D; kt += BK) {
            __syncthreads();   // guards As/Bs/dt reuse
            {   // A tile: 64 rows x 16 k (float4 per thread)
                int r = tid >> 2, kq = tid & 3;
                float4 v = *(const float4*)(fbase + (size_t)r * NUM_D + kt + kq * 4);
                As[kq * 4 + 0][r] = v.x; As[kq * 4 + 1][r] = v.y;
                As[kq * 4 + 2][r] = v.z; As[kq * 4 + 3][r] = v.w;
            }
            #pragma unroll
            for (int i = 0; i < 2; ++i) {  // B tile: 128 rows x 16 k
                int vt = tid + i * 256;
                int c = vt >> 2, kq = vt & 3;
                float4 v = *(const float4*)(cbase + (size_t)c * NUM_D + kt + kq * 4);
                Bs[kq * 4 + 0][c] = v.x; Bs[kq * 4 + 1][c] = v.y;
                Bs[kq * 4 + 2][c] = v.z; Bs[kq * 4 + 3][c] = v.w;
            }
            if (kt == 0 && tid < BN)
                s_cn[tid] = g_cnorm[(size_t)p * NUM_N + n0 + tid];
            __syncthreads();
            #pragma unroll
            for (int k = 0; k < BK; ++k) {
                float4 a0 = *(const float4*)&As[k][ty * 4];
                float4 q0 = *(const float4*)&Bs[k][tx * 8];
                float4 q1 = *(const float4*)&Bs[k][tx * 8 + 4];
                float a[4] = {a0.x, a0.y, a0.z, a0.w};
                float bb[8] = {q0.x, q0.y, q0.z, q0.w, q1.x, q1.y, q1.z, q1.w};
                #pragma unroll
                for (int i = 0; i < 4; ++i)
                    #pragma unroll
                    for (int j = 0; j < 8; ++j) acc[i][j] += a[i] * bb[j];
            }
        }
        __syncthreads();   // all smem reads of As/Bs done before dt overwrite
        #pragma unroll
        for (int i = 0; i < 4; ++i) {
            int r = ty * 4 + i;
            #pragma unroll
            for (int j = 0; j < 8; ++j) {
                int c = tx * 8 + j;
                dt[r * DT_LD + c] = s_cn[c] - 2.0f * acc[i][j];
            }
        }
        __syncthreads();
        // per-row streaming scan (4 threads/row, interleaved cols)
        for (int cc = 0; cc < 32; ++cc) {
            int c  = sq + 4 * cc;
            int gn = n0 + c;
            float d = dt[srow * DT_LD + c];
            if (gn == mypos) continue;         // masked position -> inf in reference
            lse_merge(lm, ls, d, 1.0f);
            topk_insert(d, gn, tv, ti);
        }
    }
    __syncthreads();   // scan reads of dt finished before overlay writes

    // merge the 4 per-row thread states via smem overlay on dt
    float* mv = dt;                         // 256*10 floats
    int*   mi = (int*)(dt + 2560);          // 256*10 ints
    float* mm = dt + 5120;                  // 256
    float* ms = dt + 5376;                  // 256
    #pragma unroll
    for (int i = 0; i < KTOP; ++i) { mv[tid * KTOP + i] = tv[i]; mi[tid * KTOP + i] = ti[i]; }
    mm[tid] = lm; ms[tid] = ls;
    __syncthreads();

    if (sq == 0) {
        #pragma unroll
        for (int tt = 1; tt < 4; ++tt) {
            int ot = tid + tt;
            for (int i = 0; i < KTOP; ++i) {
                float v = mv[ot * KTOP + i];
                if (v >= tv[KTOP - 1]) break;  // sorted ascending -> early out
                topk_insert(v, mi[ot * KTOP + i], tv, ti);
            }
            lse_merge(lm, ls, mm[ot], ms[ot]);
        }
        Partial* pp = &g_part[(((size_t)p * NUM_B) + b0 + srow) * NCHUNKS + chunk];
        #pragma unroll
        for (int i = 0; i < KTOP; ++i) { pp->v[i] = tv[i]; pp->id[i] = ti[i]; }
        pp->m = lm; pp->s = ls;
    }
}

// ---------------------------------------------------------------------------
// kernel 3: per-row reduction of NCHUNKS partials -> pos_vid + (y - x)
//   grid: NUM_P*NUM_B blocks, 128 threads (== NCHUNKS)
// ---------------------------------------------------------------------------
__global__ __launch_bounds__(128)
void reduce_kernel(const int* __restrict__ position,
                   const int* __restrict__ mem_pid,
                   float*     __restrict__ out)
{
    __shared__ float cv[NCHUNKS * KTOP];
    __shared__ int   ci[NCHUNKS * KTOP];
    __shared__ float rm[128], rs[128];
    __shared__ float redv[128];
    __shared__ int   redp[128];

    const int row = blockIdx.x;         // p*256 + b
    const int b   = row & 255;
    const int t   = threadIdx.x;

    const Partial* pp = &g_part[(size_t)row * NCHUNKS + t];
    #pragma unroll
    for (int i = 0; i < KTOP; ++i) { cv[t * KTOP + i] = pp->v[i]; ci[t * KTOP + i] = pp->id[i]; }
    rm[t] = pp->m; rs[t] = pp->s;
    __syncthreads();

    // LSE tree reduce over 128 partials
    for (int off = 64; off; off >>= 1) {
        if (t < off) {
            float m1 = rm[t], s1 = rs[t];
            lse_merge(m1, s1, rm[t + off], rs[t + off]);
            rm[t] = m1; rs[t] = s1;
        }
        __syncthreads();
    }

    // global top-10 via 10 rounds of block argmin over 1280 candidates
    float selv[KTOP]; int seli[KTOP];
    for (int r = 0; r < KTOP; ++r) {
        float bv = INF_F; int bp = -1;
        for (int i = t; i < NCHUNKS * KTOP; i += 128) {
            float v = cv[i];
            if (v < bv) { bv = v; bp = i; }
        }
        redv[t] = bv; redp[t] = bp;
        __syncthreads();
        for (int off = 64; off; off >>= 1) {
            if (t < off && redv[t + off] < redv[t]) {
                redv[t] = redv[t + off]; redp[t] = redp[t + off];
            }
            __syncthreads();
        }
        int wp = redp[0];
        selv[r] = redv[0];
        seli[r] = ci[wp];
        if (t == 0) cv[wp] = INF_F;
        __syncthreads();
    }

    if (t == 0) {
        float d0 = selv[0];
        float xrel = 0.0f;
        #pragma unroll
        for (int i = 0; i < KTOP; ++i) xrel += expf(-SCALE_F * (selv[i] - d0));
        float y = -SCALE_F * rm[0] + logf(rs[0]);
        float x = -SCALE_F * d0   + logf(xrel);
        g_rowdiff[row] = y - x;

        int pos = position[b];
        #pragma unroll
        for (int i = 0; i < KTOP; ++i) {
            int gi = seli[i];
            int fi = gi - (gi > pos ? 1 : 0);
            out[1 + row * KTOP + i] = (float)mem_pid[fi];
        }
    }
}

// ---------------------------------------------------------------------------
// kernel 4: deterministic loss finalize
// ---------------------------------------------------------------------------
__global__ void finalize_kernel(float* __restrict__ out) {
    __shared__ float lp[NUM_P];
    int t = threadIdx.x, w = t >> 5, lane = t & 31;
    if (w < NUM_P) {
        float s = 0.0f;
        for (int b = lane; b < NUM_B; b += 32) s += g_rowdiff[w * NUM_B + b];
        #pragma unroll
        for (int o = 16; o; o >>= 1) s += __shfl_xor_sync(0xffffffffu, s, o);
        if (lane == 0) lp[w] = s / (float)NUM_B;
    }
    __syncthreads();
    if (t == 0) {
        float L = 0.0f;
        #pragma unroll
        for (int p = 0; p < NUM_P; ++p) {
            float v = lp[p];
            if (!isnan(v)) L += v;
        }
        out[0] = L / (float)NUM_P;
    }
}

// ---------------------------------------------------------------------------
extern "C" void kernel_launch(void* const* d_in, const int* in_sizes, int n_in,
                              void* d_out, int out_size) {
    const float* feature  = (const float*)d_in[0];   // (P,B,D) f32
    const float* centers  = (const float*)d_in[1];   // (P,N,D) f32
    const int*   position = (const int*)  d_in[2];   // (B,)
    // d_in[3] camid, d_in[4] mem_camid: unused by reference
    const int*   mem_pid  = (const int*)  d_in[5];   // (N,)
    float* out = (float*)d_out;                       // [0]=loss, [1..]=pos_vid

    cnorm_kernel<<<(NUM_P * NUM_N) / 8, 256>>>(centers);
    main_kernel<<<dim3(NCHUNKS, NUM_B / BM, NUM_P), 256>>>(feature, centers, position);
    reduce_kernel<<<NUM_P * NUM_B, 128>>>(position, mem_pid, out);
    finalize_kernel<<<1, 128>>>(out);
}

// round 13
// speedup vs baseline: 1.5993x; 1.5993x over previous
#include <cuda_runtime.h>
#include <cuda_bf16.h>

#define NUM_P 4
#define NUM_B 256
#define NUM_N 65536
#define NUM_D 256
#define KTOP  10
#define SCALE_F 10.0f
#define NTILE 128
#define NCH   512              // NUM_N / NTILE
#define KCH   64
#define REST_WIN 9.0f
#define DT_LD 132
#define INF_F __int_as_float(0x7f800000)

// dynamic smem layout (bytes)
#define SM_A    0              // 256 x 128B  (bf16 features chunk)   32768
#define SM_B    32768          // 128 x 128B  (bf16 centers chunk)    16384
#define SM_DIST 49152          // 64 x 132 fp32                       33792
#define SM_CN   82944          // 128 fp32                              512
#define SM_TOTAL 83520

struct Partial { float v[KTOP]; int id[KTOP]; float m; float s; };

__device__ Partial        g_part[NUM_P * NUM_B * NCH];    // ~46 MB static scratch
__device__ unsigned short g_fh[NUM_P * NUM_B * NUM_D];    // bf16 features
__device__ float          g_rowdiff[NUM_P * NUM_B];

// ---------------- helpers ----------------
__device__ __forceinline__ unsigned smem_u32(const void* p) {
    unsigned a;
    asm("{ .reg .u64 t; cvta.to.shared.u64 t, %1; cvt.u32.u64 %0, t; }" : "=r"(a) : "l"(p));
    return a;
}
#define SWZ(bo) ((bo) ^ (((bo) >> 3) & 0x70))

__device__ __forceinline__ void mma16816(float* d, const unsigned* a, const unsigned* b) {
    asm volatile("mma.sync.aligned.m16n8k16.row.col.f32.bf16.bf16.f32 "
        "{%0,%1,%2,%3}, {%4,%5,%6,%7}, {%8,%9}, {%0,%1,%2,%3};"
        : "+f"(d[0]), "+f"(d[1]), "+f"(d[2]), "+f"(d[3])
        : "r"(a[0]), "r"(a[1]), "r"(a[2]), "r"(a[3]), "r"(b[0]), "r"(b[1]));
}
__device__ __forceinline__ void ldmx4(unsigned* r, unsigned addr) {
    asm volatile("ldmatrix.sync.aligned.m8n8.x4.shared.b16 {%0,%1,%2,%3}, [%4];"
        : "=r"(r[0]), "=r"(r[1]), "=r"(r[2]), "=r"(r[3]) : "r"(addr));
}
__device__ __forceinline__ unsigned short f2bf(float x) {
    __nv_bfloat16 h = __float2bfloat16_rn(x);
    return reinterpret_cast<unsigned short&>(h);
}
// LSE state of sum exp(-SCALE*d): m = min d seen, s = sum exp(-SCALE*(d-m))
__device__ __forceinline__ void lse_add1(float& m, float& s, float d) {
    if (s == 0.0f) { m = d; s = 1.0f; return; }
    if (d < m) { s = s * expf(SCALE_F * (d - m)) + 1.0f; m = d; }
    else        s = s + expf(SCALE_F * (m - d));
}
__device__ __forceinline__ void rest_add(float& m, float& s, float d) {
    if (d < m + REST_WIN) lse_add1(m, s, d);   // farther terms underflow in fp32
}
__device__ __forceinline__ void lse_merge(float& m, float& s, float m2, float s2) {
    if (s2 == 0.0f) return;
    if (s == 0.0f) { m = m2; s = s2; return; }
    if (m2 < m) { s = s * expf(SCALE_F * (m2 - m)) + s2; m = m2; }
    else         s = s + s2 * expf(SCALE_F * (m - m2));
}

// ---------------- kernel 0: feature fp32 -> bf16 ----------------
__global__ void feat_convert(const float* __restrict__ feature) {
    int i = blockIdx.x * blockDim.x + threadIdx.x;
    if (i < NUM_P * NUM_B * NUM_D) g_fh[i] = f2bf(feature[i]);
}

// ---------------- kernel 1: HMMA distance GEMM + scan ----------------
// grid (NCH, NUM_P), 256 threads (8 warps: 4 along M x 2 along N)
__global__ __launch_bounds__(256, 1)
void main_kernel(const float* __restrict__ centers, const int* __restrict__ position)
{
    extern __shared__ char smem[];
    const unsigned sb = smem_u32(smem);
    const int tid = threadIdx.x, lane = tid & 31, wid = tid >> 5;
    const int wm = wid >> 1, wn = wid & 1;
    const int p = blockIdx.y;
    const int n0 = blockIdx.x * NTILE;

    float acc[4][8][4];
    #pragma unroll
    for (int mt = 0; mt < 4; ++mt)
        #pragma unroll
        for (int nt = 0; nt < 8; ++nt)
            #pragma unroll
            for (int e = 0; e < 4; ++e) acc[mt][nt][e] = 0.0f;

    float sq[8];
    #pragma unroll
    for (int i = 0; i < 8; ++i) sq[i] = 0.0f;

    for (int c = 0; c < 4; ++c) {
        const int kt = c * KCH;
        // A chunk: bf16 features, 256 rows x 64 k (coalesced: 8 lanes per row)
        #pragma unroll
        for (int i = 0; i < 8; ++i) {
            int r = (tid >> 3) + i * 32, sg = tid & 7;
            *(uint4*)(smem + SM_A + SWZ((unsigned)(r * 128 + sg * 16))) =
                *(const uint4*)(g_fh + ((size_t)(p * NUM_B + r)) * NUM_D + kt + sg * 8);
        }
        // B chunk: centers fp32 -> bf16, 128 rows x 64 k, + norm accumulation
        #pragma unroll
        for (int i = 0; i < 8; ++i) {
            int v = tid + i * 256;
            int r = v >> 4, q = v & 15;
            float4 f = *(const float4*)(centers + ((size_t)p * NUM_N + n0 + r) * NUM_D + kt + q * 4);
            uint2 hp;
            asm("cvt.rn.bf16x2.f32 %0, %1, %2;" : "=r"(hp.x) : "f"(f.y), "f"(f.x));
            asm("cvt.rn.bf16x2.f32 %0, %1, %2;" : "=r"(hp.y) : "f"(f.w), "f"(f.z));
            *(uint2*)(smem + SM_B + SWZ((unsigned)(r * 128 + q * 8))) = hp;
            sq[i] += f.x * f.x + f.y * f.y + f.z * f.z + f.w * f.w;
        }
        __syncthreads();
        #pragma unroll
        for (int s = 0; s < 4; ++s) {
            unsigned af[4][4], bfr[4][4];
            #pragma unroll
            for (int mt = 0; mt < 4; ++mt) {     // A tiles (m16 x k16)
                int r = wm * 64 + mt * 16 + (lane & 7) + ((lane >> 3) & 1) * 8;
                int k = s * 16 + (lane >> 4) * 8;
                ldmx4(af[mt], sb + SM_A + SWZ((unsigned)(r * 128 + k * 2)));
            }
            #pragma unroll
            for (int g = 0; g < 4; ++g) {        // B tiles (two n8 x k16 per ldmatrix)
                int r = wn * 64 + g * 16 + (lane >> 4) * 8 + (lane & 7);
                int k = s * 16 + ((lane >> 3) & 1) * 8;
                ldmx4(bfr[g], sb + SM_B + SWZ((unsigned)(r * 128 + k * 2)));
            }
            #pragma unroll
            for (int mt = 0; mt < 4; ++mt)
                #pragma unroll
                for (int nt = 0; nt < 8; ++nt)
                    mma16816(acc[mt][nt], af[mt], &bfr[nt >> 1][(nt & 1) * 2]);
        }
        __syncthreads();
    }

    // center norms: 16 lanes per row -> s_cn
    float* s_cn = (float*)(smem + SM_CN);
    #pragma unroll
    for (int i = 0; i < 8; ++i) {
        float s = sq[i];
        s += __shfl_xor_sync(0xffffffffu, s, 8);
        s += __shfl_xor_sync(0xffffffffu, s, 4);
        s += __shfl_xor_sync(0xffffffffu, s, 2);
        s += __shfl_xor_sync(0xffffffffu, s, 1);
        if ((tid & 15) == 0) s_cn[(tid >> 4) + 16 * i] = s;
    }

    // ---- epilogue: 4 phases of 64 rows via smem dist buffer ----
    const int srow = tid >> 2, q = tid & 3;
    float* dist = (float*)(smem + SM_DIST);
    float* mv = (float*)(smem + SM_A);                 // overlay on A region
    int*   mi = (int*)(smem + SM_A + 10240);
    float* mm = (float*)(smem + SM_A + 20480);
    float* ms = (float*)(smem + SM_A + 21504);

    for (int ph = 0; ph < 4; ++ph) {
        __syncthreads();   // protect overlay readers of previous phase
        if (wm == ph) {
            #pragma unroll
            for (int mt = 0; mt < 4; ++mt)
                #pragma unroll
                for (int nt = 0; nt < 8; ++nt) {
                    int r0 = mt * 16 + (lane >> 2);
                    int c0 = wn * 64 + nt * 8 + (lane & 3) * 2;
                    *(float2*)&dist[r0 * DT_LD + c0] = make_float2(acc[mt][nt][0], acc[mt][nt][1]);
                    *(float2*)&dist[(r0 + 8) * DT_LD + c0] = make_float2(acc[mt][nt][2], acc[mt][nt][3]);
                }
        }
        __syncthreads();
        const int b = ph * 64 + srow;
        const int mypos = position[b];
        float tv[KTOP]; int ti[KTOP];
        #pragma unroll
        for (int i = 0; i < KTOP; ++i) { tv[i] = INF_F; ti[i] = -1; }
        float lm = INF_F, ls = 0.0f;

        const float* dr = dist + srow * DT_LD + q * 32;
        #pragma unroll
        for (int j = 0; j < 8; ++j) {
            float4 dv = *(const float4*)(dr + j * 4);
            #pragma unroll
            for (int e = 0; e < 4; ++e) {
                int col = q * 32 + j * 4 + e;
                float d = s_cn[col] - 2.0f * ((const float*)&dv)[e];
                int gn = n0 + col;
                if (gn == mypos) continue;
                if (d < tv[KTOP - 1]) {
                    if (ti[KTOP - 1] >= 0) rest_add(lm, ls, tv[KTOP - 1]);
                    tv[KTOP - 1] = d; ti[KTOP - 1] = gn;
                    #pragma unroll
                    for (int u = KTOP - 1; u > 0; --u) {
                        if (tv[u] < tv[u - 1]) {
                            float tf = tv[u]; tv[u] = tv[u - 1]; tv[u - 1] = tf;
                            int   tn = ti[u]; ti[u] = ti[u - 1]; ti[u - 1] = tn;
                        }
                    }
                } else {
                    rest_add(lm, ls, d);
                }
            }
        }
        #pragma unroll
        for (int i = 0; i < KTOP; ++i) { mv[tid * KTOP + i] = tv[i]; mi[tid * KTOP + i] = ti[i]; }
        mm[tid] = lm; ms[tid] = ls;
        __syncthreads();
        if (q == 0) {
            #pragma unroll
            for (int tt = 1; tt < 4; ++tt) {
                int ot = tid + tt;
                for (int i = 0; i < KTOP; ++i) {
                    float v = mv[ot * KTOP + i];
                    if (v >= tv[KTOP - 1]) break;   // sorted ascending
                    float ev = tv[KTOP - 1]; int en = ti[KTOP - 1];
                    tv[KTOP - 1] = v; ti[KTOP - 1] = mi[ot * KTOP + i];
                    if (en >= 0) rest_add(lm, ls, ev);
                    #pragma unroll
                    for (int u = KTOP - 1; u > 0; --u) {
                        if (tv[u] < tv[u - 1]) {
                            float tf = tv[u]; tv[u] = tv[u - 1]; tv[u - 1] = tf;
                            int   tn = ti[u]; ti[u] = ti[u - 1]; ti[u - 1] = tn;
                        }
                    }
                }
                lse_merge(lm, ls, mm[ot], ms[ot]);
            }
            Partial* pp = &g_part[((size_t)(p * NUM_B + b)) * NCH + blockIdx.x];
            #pragma unroll
            for (int i = 0; i < KTOP; ++i) { pp->v[i] = tv[i]; pp->id[i] = ti[i]; }
            pp->m = lm; pp->s = ls;
        }
    }
}

// ---------------- kernel 2: per-row merge of 512 partials + exact refine ----------------
// grid NUM_P*NUM_B, 256 threads (each pre-merges 2 chunks)
__global__ __launch_bounds__(256)
void reduce_kernel(const float* __restrict__ feature,
                   const float* __restrict__ centers,
                   const int*   __restrict__ position,
                   const int*   __restrict__ mem_pid,
                   float*       __restrict__ out)
{
    __shared__ float cv[256 * KTOP];
    __shared__ int   ci[256 * KTOP];
    __shared__ float s_rm[256], s_rs[256];
    __shared__ __align__(16) float s_feat[256];
    __shared__ float wvv[8]; __shared__ int wii[8], wtt[8];
    __shared__ float s_selv[16]; __shared__ int s_selid[16];
    __shared__ int   s_wtid;
    __shared__ float s_ed[16];

    const int row = blockIdx.x;              // p*256 + b
    const int p = row >> 8, b = row & 255;
    const int t = threadIdx.x, lane = t & 31, w = t >> 5;

    const Partial* p0 = &g_part[(size_t)row * NCH + 2 * t];
    const Partial* p1 = p0 + 1;
    float av[KTOP], bv[KTOP]; int ai[KTOP], bi[KTOP];
    #pragma unroll
    for (int i = 0; i < KTOP; ++i) {
        av[i] = p0->v[i]; ai[i] = p0->id[i];
        bv[i] = p1->v[i]; bi[i] = p1->id[i];
    }
    float lm = p0->m, ls = p0->s;
    lse_merge(lm, ls, p1->m, p1->s);
    {   // merge two sorted 10-lists, keep 10, evictions -> rest
        int i = 0, j = 0;
        #pragma unroll
        for (int r = 0; r < KTOP; ++r) {
            bool ta = (av[i] < bv[j]) || (av[i] == bv[j] && ai[i] <= bi[j]);
            cv[t * KTOP + r] = ta ? av[i] : bv[j];
            ci[t * KTOP + r] = ta ? ai[i] : bi[j];
            if (ta) ++i; else ++j;
        }
        for (; i < KTOP; ++i) { if (av[i] >= lm + REST_WIN) break; lse_add1(lm, ls, av[i]); }
        for (; j < KTOP; ++j) { if (bv[j] >= lm + REST_WIN) break; lse_add1(lm, ls, bv[j]); }
    }
    s_feat[t] = feature[((size_t)p * NUM_B + b) * NUM_D + t];
    __syncthreads();

    // top-16 selection across 256 sorted lists
    int ptr = 0;
    for (int r = 0; r < 16; ++r) {
        float hv; int hid;
        if (ptr < KTOP) { hv = cv[t * KTOP + ptr]; hid = ci[t * KTOP + ptr]; }
        else            { hv = INF_F; hid = 0x7fffffff; }
        int ht = t;
        #pragma unroll
        for (int o = 16; o; o >>= 1) {
            float ov = __shfl_xor_sync(0xffffffffu, hv, o);
            int   oi = __shfl_xor_sync(0xffffffffu, hid, o);
            int   ot = __shfl_xor_sync(0xffffffffu, ht, o);
            if (ov < hv || (ov == hv && oi < hid)) { hv = ov; hid = oi; ht = ot; }
        }
        if (lane == 0) { wvv[w] = hv; wii[w] = hid; wtt[w] = ht; }
        __syncthreads();
        if (t == 0) {
            float bvx = wvv[0]; int bix = wii[0], btx = wtt[0];
            #pragma unroll
            for (int u = 1; u < 8; ++u)
                if (wvv[u] < bvx || (wvv[u] == bvx && wii[u] < bix)) { bvx = wvv[u]; bix = wii[u]; btx = wtt[u]; }
            s_selv[r] = bvx; s_selid[r] = bix; s_wtid = btx;
        }
        __syncthreads();
        if (t == s_wtid) ptr++;
        __syncthreads();
    }

    // unselected candidates -> rest (sorted, early break)
    for (int i = ptr; i < KTOP; ++i) {
        float d = cv[t * KTOP + i];
        if (d >= lm + REST_WIN) break;
        lse_add1(lm, ls, d);
    }
    s_rm[t] = lm; s_rs[t] = ls;
    __syncthreads();
    for (int off = 128; off; off >>= 1) {
        if (t < off) {
            float m1 = s_rm[t], s1 = s_rs[t];
            lse_merge(m1, s1, s_rm[t + off], s_rs[t + off]);
            s_rm[t] = m1; s_rs[t] = s1;
        }
        __syncthreads();
    }

    // exact fp32 refine of the 16 candidates: d = ||c||^2 - 2 f.c
    for (int cp = 0; cp < 2; ++cp) {
        int c = w + cp * 8;
        int id = s_selid[c];
        const float4* crow = (const float4*)(centers + ((size_t)p * NUM_N + id) * NUM_D);
        const float4* frow = (const float4*)s_feat;
        float dot = 0.0f, cn = 0.0f;
        #pragma unroll
        for (int j = 0; j < 2; ++j) {
            float4 cc = crow[lane + j * 32];
            float4 ff = frow[lane + j * 32];
            dot += cc.x * ff.x + cc.y * ff.y + cc.z * ff.z + cc.w * ff.w;
            cn  += cc.x * cc.x + cc.y * cc.y + cc.z * cc.z + cc.w * cc.w;
        }
        #pragma unroll
        for (int o = 16; o; o >>= 1) {
            dot += __shfl_xor_sync(0xffffffffu, dot, o);
            cn  += __shfl_xor_sync(0xffffffffu, cn, o);
        }
        if (lane == 0) s_ed[c] = cn - 2.0f * dot;
    }
    __syncthreads();

    if (t == 0) {
        float ed[16]; int eid[16];
        #pragma unroll
        for (int i = 0; i < 16; ++i) { ed[i] = s_ed[i]; eid[i] = s_selid[i]; }
        for (int i = 1; i < 16; ++i) {          // insertion sort by (d, id)
            float dv = ed[i]; int di = eid[i]; int j = i - 1;
            while (j >= 0 && (ed[j] > dv || (ed[j] == dv && eid[j] > di))) {
                ed[j + 1] = ed[j]; eid[j + 1] = eid[j]; --j;
            }
            ed[j + 1] = dv; eid[j + 1] = di;
        }
        float m0 = ed[0], xs = 0.0f;
        #pragma unroll
        for (int i = 0; i < KTOP; ++i) xs += expf(-SCALE_F * (ed[i] - m0));
        float rm0 = s_rm[0], rs0 = s_rs[0];
        for (int i = KTOP; i < 16; ++i) rest_add(rm0, rs0, ed[i]);
        float ym = m0, ysum = xs;
        lse_merge(ym, ysum, rm0, rs0);
        float y = -SCALE_F * ym + logf(ysum);
        float x = -SCALE_F * m0 + logf(xs);
        g_rowdiff[row] = y - x;

        int pos = position[b];
        #pragma unroll
        for (int i = 0; i < KTOP; ++i) {
            int gi = eid[i];
            int fi = gi - (gi > pos ? 1 : 0);
            out[1 + row * KTOP + i] = (float)mem_pid[fi];
        }
    }
}

// ---------------- kernel 3: deterministic loss finalize ----------------
__global__ void finalize_kernel(float* __restrict__ out) {
    __shared__ float lp[NUM_P];
    int t = threadIdx.x, w = t >> 5, lane = t & 31;
    if (w < NUM_P) {
        float s = 0.0f;
        for (int b = lane; b < NUM_B; b += 32) s += g_rowdiff[w * NUM_B + b];
        #pragma unroll
        for (int o = 16; o; o >>= 1) s += __shfl_xor_sync(0xffffffffu, s, o);
        if (lane == 0) lp[w] = s / (float)NUM_B;
    }
    __syncthreads();
    if (t == 0) {
        float L = 0.0f;
        #pragma unroll
        for (int p = 0; p < NUM_P; ++p) { float v = lp[p]; if (!isnan(v)) L += v; }
        out[0] = L / (float)NUM_P;
    }
}

// ---------------------------------------------------------------------------
extern "C" void kernel_launch(void* const* d_in, const int* in_sizes, int n_in,
                              void* d_out, int out_size) {
    const float* feature  = (const float*)d_in[0];
    const float* centers  = (const float*)d_in[1];
    const int*   position = (const int*)  d_in[2];
    const int*   mem_pid  = (const int*)  d_in[5];
    float* out = (float*)d_out;

    static int attr_done = 0;
    if (!attr_done) {
        cudaFuncSetAttribute(main_kernel, cudaFuncAttributeMaxDynamicSharedMemorySize, SM_TOTAL);
        attr_done = 1;
    }

    feat_convert<<<(NUM_P * NUM_B * NUM_D) / 256, 256>>>(feature);
    main_kernel<<<dim3(NCH, NUM_P), 256, SM_TOTAL>>>(centers, position);
    reduce_kernel<<<NUM_P * NUM_B, 256>>>(feature, centers, position, mem_pid, out);
    finalize_kernel<<<1, 128>>>(out);
}

// round 15
// speedup vs baseline: 1.8927x; 1.1835x over previous
#include <cuda_runtime.h>
#include <cuda_bf16.h>

#define NUM_P 4
#define NUM_B 256
#define NUM_N 65536
#define NUM_D 256
#define KTOP  10
#define SCALE_F 10.0f
#define NTILE 64
#define NCH   1024             // NUM_N / NTILE
#define KCH   64
#define REST_WIN 9.0f
#define DT_LD 68
#define INF_F __int_as_float(0x7f800000)

// dynamic smem layout (bytes)
#define SM_A    0              // 256 rows x 128B (bf16 feature chunk)   32768
#define SM_B    32768          // 64 rows x 128B (bf16 center chunk)      8192
#define SM_CN   40960          // 64 fp32 center norms
#define SM_TOTAL 41472
// epilogue overlay on A+B region (after last MMA chunk)
#define SM_DIST 0              // 64 x 68 fp32          17408
#define SM_MV   17408          // 256*10 fp32           10240
#define SM_MI   27648          // 256*10 int            10240
#define SM_MM   37888          // 256 fp32
#define SM_MS   38912          // 256 fp32

struct Partial { float v[KTOP]; int id[KTOP]; float m; float s; };

__device__ Partial        g_part[NUM_P * NUM_B * NCH];    // ~92 MB static scratch
__device__ unsigned short g_fh[NUM_P * NUM_B * NUM_D];    // bf16 features
__device__ float          g_rowdiff[NUM_P * NUM_B];

// ---------------- helpers ----------------
__device__ __forceinline__ unsigned smem_u32(const void* p) {
    unsigned a;
    asm("{ .reg .u64 t; cvta.to.shared.u64 t, %1; cvt.u32.u64 %0, t; }" : "=r"(a) : "l"(p));
    return a;
}
#define SWZ(bo) ((bo) ^ (((bo) >> 3) & 0x70))

__device__ __forceinline__ void mma16816(float* d, const unsigned* a, const unsigned* b) {
    asm volatile("mma.sync.aligned.m16n8k16.row.col.f32.bf16.bf16.f32 "
        "{%0,%1,%2,%3}, {%4,%5,%6,%7}, {%8,%9}, {%0,%1,%2,%3};"
        : "+f"(d[0]), "+f"(d[1]), "+f"(d[2]), "+f"(d[3])
        : "r"(a[0]), "r"(a[1]), "r"(a[2]), "r"(a[3]), "r"(b[0]), "r"(b[1]));
}
__device__ __forceinline__ void ldmx4(unsigned* r, unsigned addr) {
    asm volatile("ldmatrix.sync.aligned.m8n8.x4.shared.b16 {%0,%1,%2,%3}, [%4];"
        : "=r"(r[0]), "=r"(r[1]), "=r"(r[2]), "=r"(r[3]) : "r"(addr));
}
__device__ __forceinline__ unsigned short f2bf(float x) {
    __nv_bfloat16 h = __float2bfloat16_rn(x);
    return reinterpret_cast<unsigned short&>(h);
}
// LSE state of sum exp(-SCALE*d): m = min d seen, s = sum exp(-SCALE*(d-m))
__device__ __forceinline__ void lse_add1(float& m, float& s, float d) {
    if (s == 0.0f) { m = d; s = 1.0f; return; }
    if (d < m) { s = s * expf(SCALE_F * (d - m)) + 1.0f; m = d; }
    else        s = s + expf(SCALE_F * (m - d));
}
__device__ __forceinline__ void rest_add(float& m, float& s, float d) {
    if (d < m + REST_WIN) lse_add1(m, s, d);   // farther terms underflow in fp32
}
__device__ __forceinline__ void lse_merge(float& m, float& s, float m2, float s2) {
    if (s2 == 0.0f) return;
    if (s == 0.0f) { m = m2; s = s2; return; }
    if (m2 < m) { s = s * expf(SCALE_F * (m2 - m)) + s2; m = m2; }
    else         s = s + s2 * expf(SCALE_F * (m - m2));
}

// ---------------- kernel 0: feature fp32 -> bf16 ----------------
__global__ void feat_convert(const float* __restrict__ feature) {
    int i = blockIdx.x * blockDim.x + threadIdx.x;
    if (i < NUM_P * NUM_B * NUM_D) g_fh[i] = f2bf(feature[i]);
}

// ---------------- kernel 1: HMMA distance GEMM + scan ----------------
// grid (NCH, NUM_P), 256 threads (8 warps, each 32 rows x 64 cols), 2 CTAs/SM
__global__ __launch_bounds__(256, 2)
void main_kernel(const float* __restrict__ centers, const int* __restrict__ position)
{
    extern __shared__ char smem[];
    const unsigned sb = smem_u32(smem);
    const int tid = threadIdx.x, lane = tid & 31, wid = tid >> 5;
    const int wm = wid;                    // 8 M-warps of 32 rows
    const int p = blockIdx.y;
    const int n0 = blockIdx.x * NTILE;

    float acc[2][8][4];                    // 64 regs: 32 rows x 64 cols / 32 lanes
    #pragma unroll
    for (int mt = 0; mt < 2; ++mt)
        #pragma unroll
        for (int nt = 0; nt < 8; ++nt)
            #pragma unroll
            for (int e = 0; e < 4; ++e) acc[mt][nt][e] = 0.0f;

    float sq[4];
    #pragma unroll
    for (int i = 0; i < 4; ++i) sq[i] = 0.0f;

    for (int c = 0; c < 4; ++c) {
        const int kt = c * KCH;
        // A chunk: bf16 features, 256 rows x 64 k
        #pragma unroll
        for (int i = 0; i < 8; ++i) {
            int r = (tid >> 3) + i * 32, sg = tid & 7;
            *(uint4*)(smem + SM_A + SWZ((unsigned)(r * 128 + sg * 16))) =
                *(const uint4*)(g_fh + ((size_t)(p * NUM_B + r)) * NUM_D + kt + sg * 8);
        }
        // B chunk: centers fp32 -> bf16, 64 rows x 64 k, + norm accumulation
        #pragma unroll
        for (int i = 0; i < 4; ++i) {
            int v = tid + i * 256;
            int r = v >> 4, q = v & 15;
            float4 f = *(const float4*)(centers + ((size_t)p * NUM_N + n0 + r) * NUM_D + kt + q * 4);
            uint2 hp;
            asm("cvt.rn.bf16x2.f32 %0, %1, %2;" : "=r"(hp.x) : "f"(f.y), "f"(f.x));
            asm("cvt.rn.bf16x2.f32 %0, %1, %2;" : "=r"(hp.y) : "f"(f.w), "f"(f.z));
            *(uint2*)(smem + SM_B + SWZ((unsigned)(r * 128 + q * 8))) = hp;
            sq[i] += f.x * f.x + f.y * f.y + f.z * f.z + f.w * f.w;
        }
        __syncthreads();
        #pragma unroll
        for (int s = 0; s < 4; ++s) {
            unsigned af[2][4], bfr[4][4];
            #pragma unroll
            for (int mt = 0; mt < 2; ++mt) {   // A tiles (m16 x k16)
                int r = wm * 32 + mt * 16 + (lane & 7) + ((lane >> 3) & 1) * 8;
                int k = s * 16 + (lane >> 4) * 8;
                ldmx4(af[mt], sb + SM_A + SWZ((unsigned)(r * 128 + k * 2)));
            }
            #pragma unroll
            for (int g = 0; g < 4; ++g) {      // B tiles (two n8 x k16 per ldmatrix)
                int r = g * 16 + (lane >> 4) * 8 + (lane & 7);
                int k = s * 16 + ((lane >> 3) & 1) * 8;
                ldmx4(bfr[g], sb + SM_B + SWZ((unsigned)(r * 128 + k * 2)));
            }
            #pragma unroll
            for (int mt = 0; mt < 2; ++mt)
                #pragma unroll
                for (int nt = 0; nt < 8; ++nt)
                    mma16816(acc[mt][nt], af[mt], &bfr[nt >> 1][(nt & 1) * 2]);
        }
        __syncthreads();
    }

    // center norms: 16 lanes per row -> s_cn (64 values)
    float* s_cn = (float*)(smem + SM_CN);
    #pragma unroll
    for (int i = 0; i < 4; ++i) {
        float s = sq[i];
        s += __shfl_xor_sync(0xffffffffu, s, 8);
        s += __shfl_xor_sync(0xffffffffu, s, 4);
        s += __shfl_xor_sync(0xffffffffu, s, 2);
        s += __shfl_xor_sync(0xffffffffu, s, 1);
        if ((tid & 15) == 0) s_cn[(tid >> 4) + 16 * i] = s;
    }

    // ---- epilogue: 4 phases of 64 rows via smem dist buffer (overlay on A/B) ----
    const int srow = tid >> 2, q = tid & 3;
    float* dist = (float*)(smem + SM_DIST);
    float* mv = (float*)(smem + SM_MV);
    int*   mi = (int*)(smem + SM_MI);
    float* mm = (float*)(smem + SM_MM);
    float* ms = (float*)(smem + SM_MS);

    for (int ph = 0; ph < 4; ++ph) {
        __syncthreads();
        if ((wm >> 1) == ph) {             // warps 2ph, 2ph+1 own rows ph*64..+63
            #pragma unroll
            for (int mt = 0; mt < 2; ++mt)
                #pragma unroll
                for (int nt = 0; nt < 8; ++nt) {
                    int r0 = (wm & 1) * 32 + mt * 16 + (lane >> 2);
                    int c0 = nt * 8 + (lane & 3) * 2;
                    *(float2*)&dist[r0 * DT_LD + c0] = make_float2(acc[mt][nt][0], acc[mt][nt][1]);
                    *(float2*)&dist[(r0 + 8) * DT_LD + c0] = make_float2(acc[mt][nt][2], acc[mt][nt][3]);
                }
        }
        __syncthreads();
        const int b = ph * 64 + srow;
        const int mypos = position[b];
        float tv[KTOP]; int ti[KTOP];
        #pragma unroll
        for (int i = 0; i < KTOP; ++i) { tv[i] = INF_F; ti[i] = -1; }
        float lm = INF_F, ls = 0.0f;

        const float* dr = dist + srow * DT_LD + q * 16;
        #pragma unroll
        for (int j = 0; j < 4; ++j) {
            float4 dv = *(const float4*)(dr + j * 4);
            #pragma unroll
            for (int e = 0; e < 4; ++e) {
                int col = q * 16 + j * 4 + e;
                float d = s_cn[col] - 2.0f * ((const float*)&dv)[e];
                int gn = n0 + col;
                if (gn == mypos) continue;
                if (d < tv[KTOP - 1]) {
                    if (ti[KTOP - 1] >= 0) rest_add(lm, ls, tv[KTOP - 1]);
                    tv[KTOP - 1] = d; ti[KTOP - 1] = gn;
                    #pragma unroll
                    for (int u = KTOP - 1; u > 0; --u) {
                        if (tv[u] < tv[u - 1]) {
                            float tf = tv[u]; tv[u] = tv[u - 1]; tv[u - 1] = tf;
                            int   tn = ti[u]; ti[u] = ti[u - 1]; ti[u - 1] = tn;
                        }
                    }
                } else {
                    rest_add(lm, ls, d);
                }
            }
        }
        #pragma unroll
        for (int i = 0; i < KTOP; ++i) { mv[tid * KTOP + i] = tv[i]; mi[tid * KTOP + i] = ti[i]; }
        mm[tid] = lm; ms[tid] = ls;
        __syncthreads();
        if (q == 0) {
            #pragma unroll
            for (int tt = 1; tt < 4; ++tt) {
                int ot = tid + tt;
                int i = 0;
                for (; i < KTOP; ++i) {
                    float v = mv[ot * KTOP + i];
                    if (v >= tv[KTOP - 1]) break;   // sorted ascending
                    float ev = tv[KTOP - 1]; int en = ti[KTOP - 1];
                    tv[KTOP - 1] = v; ti[KTOP - 1] = mi[ot * KTOP + i];
                    if (en >= 0) rest_add(lm, ls, ev);
                    #pragma unroll
                    for (int u = KTOP - 1; u > 0; --u) {
                        if (tv[u] < tv[u - 1]) {
                            float tf = tv[u]; tv[u] = tv[u - 1]; tv[u - 1] = tf;
                            int   tn = ti[u]; ti[u] = ti[u - 1]; ti[u - 1] = tn;
                        }
                    }
                }
                for (; i < KTOP; ++i) {             // leftovers -> rest (windowed)
                    float v = mv[ot * KTOP + i];
                    if (mi[ot * KTOP + i] < 0 || v >= lm + REST_WIN) break;
                    lse_add1(lm, ls, v);
                }
                lse_merge(lm, ls, mm[ot], ms[ot]);
            }
            Partial* pp = &g_part[((size_t)(p * NUM_B + b)) * NCH + blockIdx.x];
            #pragma unroll
            for (int i = 0; i < KTOP; ++i) { pp->v[i] = tv[i]; pp->id[i] = ti[i]; }
            pp->m = lm; pp->s = ls;
        }
    }
}

// ---------------- kernel 2: per-row merge of 1024 partials + exact refine ----------------
// grid NUM_P*NUM_B, 256 threads (each pre-merges 4 chunks)
__global__ __launch_bounds__(256)
void reduce_kernel(const float* __restrict__ feature,
                   const float* __restrict__ centers,
                   const int*   __restrict__ position,
                   const int*   __restrict__ mem_pid,
                   float*       __restrict__ out)
{
    __shared__ float cv[256 * KTOP];
    __shared__ int   ci[256 * KTOP];
    __shared__ float s_rm[256], s_rs[256];
    __shared__ __align__(16) float s_feat[256];
    __shared__ float wvv[8]; __shared__ int wii[8], wtt[8];
    __shared__ float s_selv[16]; __shared__ int s_selid[16];
    __shared__ int   s_wtid;
    __shared__ float s_ed[16];

    const int row = blockIdx.x;              // p*256 + b
    const int p = row >> 8, b = row & 255;
    const int t = threadIdx.x, lane = t & 31, w = t >> 5;

    // pre-merge 4 consecutive chunk partials into one sorted 10-list + rest
    const Partial* pb = &g_part[(size_t)row * NCH + 4 * t];
    float tv[KTOP]; int ti[KTOP];
    #pragma unroll
    for (int i = 0; i < KTOP; ++i) { tv[i] = pb->v[i]; ti[i] = pb->id[i]; }
    float lm = pb->m, ls = pb->s;
    for (int cc = 1; cc < 4; ++cc) {
        const Partial* pc = pb + cc;
        lse_merge(lm, ls, pc->m, pc->s);
        int i = 0;
        for (; i < KTOP; ++i) {
            float v = pc->v[i];
            if (v >= tv[KTOP - 1]) break;
            float ev = tv[KTOP - 1]; int en = ti[KTOP - 1];
            tv[KTOP - 1] = v; ti[KTOP - 1] = pc->id[i];
            if (en >= 0) rest_add(lm, ls, ev);
            #pragma unroll
            for (int u = KTOP - 1; u > 0; --u) {
                if (tv[u] < tv[u - 1]) {
                    float tf = tv[u]; tv[u] = tv[u - 1]; tv[u - 1] = tf;
                    int   tn = ti[u]; ti[u] = ti[u - 1]; ti[u - 1] = tn;
                }
            }
        }
        for (; i < KTOP; ++i) {
            float v = pc->v[i];
            if (pc->id[i] < 0 || v >= lm + REST_WIN) break;
            lse_add1(lm, ls, v);
        }
    }
    #pragma unroll
    for (int i = 0; i < KTOP; ++i) { cv[t * KTOP + i] = tv[i]; ci[t * KTOP + i] = ti[i]; }
    s_feat[t] = feature[((size_t)p * NUM_B + b) * NUM_D + t];
    __syncthreads();

    // top-16 selection across 256 sorted lists
    int ptr = 0;
    for (int r = 0; r < 16; ++r) {
        float hv; int hid;
        if (ptr < KTOP) { hv = cv[t * KTOP + ptr]; hid = ci[t * KTOP + ptr]; }
        else            { hv = INF_F; hid = 0x7fffffff; }
        int ht = t;
        #pragma unroll
        for (int o = 16; o; o >>= 1) {
            float ov = __shfl_xor_sync(0xffffffffu, hv, o);
            int   oi = __shfl_xor_sync(0xffffffffu, hid, o);
            int   ot = __shfl_xor_sync(0xffffffffu, ht, o);
            if (ov < hv || (ov == hv && oi < hid)) { hv = ov; hid = oi; ht = ot; }
        }
        if (lane == 0) { wvv[w] = hv; wii[w] = hid; wtt[w] = ht; }
        __syncthreads();
        if (t == 0) {
            float bvx = wvv[0]; int bix = wii[0], btx = wtt[0];
            #pragma unroll
            for (int u = 1; u < 8; ++u)
                if (wvv[u] < bvx || (wvv[u] == bvx && wii[u] < bix)) { bvx = wvv[u]; bix = wii[u]; btx = wtt[u]; }
            s_selv[r] = bvx; s_selid[r] = bix; s_wtid = btx;
        }
        __syncthreads();
        if (t == s_wtid) ptr++;
        __syncthreads();
    }

    // unselected candidates -> rest (sorted, early break)
    for (int i = ptr; i < KTOP; ++i) {
        float d = cv[t * KTOP + i];
        if (ci[t * KTOP + i] < 0 || d >= lm + REST_WIN) break;
        lse_add1(lm, ls, d);
    }
    s_rm[t] = lm; s_rs[t] = ls;
    __syncthreads();
    for (int off = 128; off; off >>= 1) {
        if (t < off) {
            float m1 = s_rm[t], s1 = s_rs[t];
            lse_merge(m1, s1, s_rm[t + off], s_rs[t + off]);
            s_rm[t] = m1; s_rs[t] = s1;
        }
        __syncthreads();
    }

    // exact fp32 refine of the 16 candidates: d = ||c||^2 - 2 f.c
    for (int cp = 0; cp < 2; ++cp) {
        int c = w + cp * 8;
        int id = s_selid[c];
        const float4* crow = (const float4*)(centers + ((size_t)p * NUM_N + id) * NUM_D);
        const float4* frow = (const float4*)s_feat;
        float dot = 0.0f, cn = 0.0f;
        #pragma unroll
        for (int j = 0; j < 2; ++j) {
            float4 cc = crow[lane + j * 32];
            float4 ff = frow[lane + j * 32];
            dot += cc.x * ff.x + cc.y * ff.y + cc.z * ff.z + cc.w * ff.w;
            cn  += cc.x * cc.x + cc.y * cc.y + cc.z * cc.z + cc.w * cc.w;
        }
        #pragma unroll
        for (int o = 16; o; o >>= 1) {
            dot += __shfl_xor_sync(0xffffffffu, dot, o);
            cn  += __shfl_xor_sync(0xffffffffu, cn, o);
        }
        if (lane == 0) s_ed[c] = cn - 2.0f * dot;
    }
    __syncthreads();

    if (t == 0) {
        float ed[16]; int eid[16];
        #pragma unroll
        for (int i = 0; i < 16; ++i) { ed[i] = s_ed[i]; eid[i] = s_selid[i]; }
        for (int i = 1; i < 16; ++i) {          // insertion sort by (d, id)
            float dv = ed[i]; int di = eid[i]; int j = i - 1;
            while (j >= 0 && (ed[j] > dv || (ed[j] == dv && eid[j] > di))) {
                ed[j + 1] = ed[j]; eid[j + 1] = eid[j]; --j;
            }
            ed[j + 1] = dv; eid[j + 1] = di;
        }
        float m0 = ed[0], xs = 0.0f;
        #pragma unroll
        for (int i = 0; i < KTOP; ++i) xs += expf(-SCALE_F * (ed[i] - m0));
        float rm0 = s_rm[0], rs0 = s_rs[0];
        for (int i = KTOP; i < 16; ++i) rest_add(rm0, rs0, ed[i]);
        float ym = m0, ysum = xs;
        lse_merge(ym, ysum, rm0, rs0);
        float y = -SCALE_F * ym + logf(ysum);
        float x = -SCALE_F * m0 + logf(xs);
        g_rowdiff[row] = y - x;

        int pos = position[b];
        #pragma unroll
        for (int i = 0; i < KTOP; ++i) {
            int gi = eid[i];
            int fi = gi - (gi > pos ? 1 : 0);
            out[1 + row * KTOP + i] = (float)mem_pid[fi];
        }
    }
}

// ---------------- kernel 3: deterministic loss finalize ----------------
__global__ void finalize_kernel(float* __restrict__ out) {
    __shared__ float lp[NUM_P];
    int t = threadIdx.x, w = t >> 5, lane = t & 31;
    if (w < NUM_P) {
        float s = 0.0f;
        for (int b = lane; b < NUM_B; b += 32) s += g_rowdiff[w * NUM_B + b];
        #pragma unroll
        for (int o = 16; o; o >>= 1) s += __shfl_xor_sync(0xffffffffu, s, o);
        if (lane == 0) lp[w] = s / (float)NUM_B;
    }
    __syncthreads();
    if (t == 0) {
        float L = 0.0f;
        #pragma unroll
        for (int p = 0; p < NUM_P; ++p) { float v = lp[p]; if (!isnan(v)) L += v; }
        out[0] = L / (float)NUM_P;
    }
}

// ---------------------------------------------------------------------------
extern "C" void kernel_launch(void* const* d_in, const int* in_sizes, int n_in,
                              void* d_out, int out_size) {
    const float* feature  = (const float*)d_in[0];
    const float* centers  = (const float*)d_in[1];
    const int*   position = (const int*)  d_in[2];
    const int*   mem_pid  = (const int*)  d_in[5];
    float* out = (float*)d_out;

    cudaFuncSetAttribute(main_kernel, cudaFuncAttributeMaxDynamicSharedMemorySize, SM_TOTAL);

    feat_convert<<<(NUM_P * NUM_B * NUM_D) / 256, 256>>>(feature);
    main_kernel<<<dim3(NCH, NUM_P), 256, SM_TOTAL>>>(centers, position);
    reduce_kernel<<<NUM_P * NUM_B, 256>>>(feature, centers, position, mem_pid, out);
    finalize_kernel<<<1, 128>>>(out);
}